// round 6
// baseline (speedup 1.0000x reference)
#include <cuda_runtime.h>
#include <cstdint>

// x: (131072, 28, 28) fp32. rows = 4 int32, cols = 4 int32.
// out[i,h,w] = mute(x) if (h in rows) || (w in cols) else x
// mute idempotent -> single mask test. Mask = f(float4_index % 196), smem LUT.
// Persistent grid-stride version: one wave (148*8 CTAs), each loops over chunks
// of 1024 float4s -> removes ~20 wave transitions + 24k CTA prologues.

static constexpr int HW4 = 196;                     // float4 positions per image
static constexpr long long NELEM = 131072LL * 784;  // 102,760,448
static constexpr int N4 = (int)(NELEM / 4);         // 25,690,112 = 25088 * 1024
static constexpr int UNROLL = 4;
static constexpr int THREADS = 256;
static constexpr int CHUNK = THREADS * UNROLL;      // 1024 float4s
static constexpr int NCHUNKS = N4 / CHUNK;          // 25,088 exact
static constexpr int STEP = 256 % HW4;              // 60
static constexpr int GRID = 148 * 8;                // one full wave

__device__ __forceinline__ float mute1(float x) {
    unsigned b  = __float_as_uint(x);
    unsigned ef = b & 0x7F800000u;                   // exponent field in place
    unsigned b2 = (b & 0x807FFFFFu) | 0x3F000000u;   // exponent -> 126
    // biased exp in [128,254]  <=>  ef in [0x40000000, 0x7F800000)
    return __uint_as_float((ef - 0x40000000u < 0x3F800000u) ? b2 : b);
}

__global__ void __launch_bounds__(THREADS) mute_kernel(
    const float4* __restrict__ x,
    const int* __restrict__ rows,
    const int* __restrict__ cols,
    float4* __restrict__ out)
{
    __shared__ unsigned char lut[HW4];

    int tid = threadIdx.x;
    if (tid < HW4) {
        int p = tid * 4;          // element offset within 28x28 image
        int h = p / 28;
        int w = p - h * 28;       // float4 never crosses a row (4 | 28)
        int r0 = rows[0], r1 = rows[1], r2 = rows[2], r3 = rows[3];
        int c0 = cols[0], c1 = cols[1], c2 = cols[2], c3 = cols[3];
        bool rm = (h == r0) | (h == r1) | (h == r2) | (h == r3);
        unsigned m = 0;
        #pragma unroll
        for (int k = 0; k < 4; k++) {
            bool cm = (w + k == c0) | (w + k == c1) | (w + k == c2) | (w + k == c3);
            if (rm | cm) m |= (1u << k);
        }
        lut[tid] = (unsigned char)m;
    }
    __syncthreads();

    for (int c = blockIdx.x; c < NCHUNKS; c += GRID) {
        int base = c * CHUNK + tid;

        // Front-batch 4 LDG.128s (MLP=4)
        float4 v[UNROLL];
        #pragma unroll
        for (int k = 0; k < UNROLL; k++) {
            v[k] = x[base + k * THREADS];
        }

        // Incremental phase: (base + k*256) % 196
        int ph = base % HW4;

        #pragma unroll
        for (int k = 0; k < UNROLL; k++) {
            unsigned m = lut[ph];
            v[k].x = (m & 1u) ? mute1(v[k].x) : v[k].x;
            v[k].y = (m & 2u) ? mute1(v[k].y) : v[k].y;
            v[k].z = (m & 4u) ? mute1(v[k].z) : v[k].z;
            v[k].w = (m & 8u) ? mute1(v[k].w) : v[k].w;
            out[base + k * THREADS] = v[k];
            ph += STEP;
            if (ph >= HW4) ph -= HW4;
        }
    }
}

extern "C" void kernel_launch(void* const* d_in, const int* in_sizes, int n_in,
                              void* d_out, int out_size) {
    const float4* x = (const float4*)d_in[0];
    const int* rows = (const int*)d_in[1];
    const int* cols = (const int*)d_in[2];
    float4* out     = (float4*)d_out;

    mute_kernel<<<GRID, THREADS>>>(x, rows, cols, out);
}

// round 9
// speedup vs baseline: 1.1271x; 1.1271x over previous
#include <cuda_runtime.h>
#include <cstdint>

// x: (131072, 28, 28) fp32. rows = 4 int32, cols = 4 int32.
// out[i,h,w] = mute(x) if (h in rows) || (w in cols) else x
// mute idempotent -> single mask test. Mask = f(float4_index % 196), smem LUT.
// R5 per-thread shape (UNROLL=4, MLP=4, lean mute, incremental phase), but
// THREADS=512 -> half the CTAs, same 64-warp/SM occupancy.

static constexpr int HW4 = 196;                     // float4 positions per image
static constexpr long long NELEM = 131072LL * 784;  // 102,760,448
static constexpr int N4 = (int)(NELEM / 4);         // 25,690,112 = 12544 * 2048
static constexpr int UNROLL = 4;
static constexpr int THREADS = 512;
static constexpr int STEP = (THREADS % HW4);        // 512 % 196 = 120

__device__ __forceinline__ float mute1(float x) {
    unsigned b  = __float_as_uint(x);
    unsigned ef = b & 0x7F800000u;                   // exponent field in place
    unsigned b2 = (b & 0x807FFFFFu) | 0x3F000000u;   // exponent -> 126
    // biased exp in [128,254]  <=>  ef in [0x40000000, 0x7F800000)
    return __uint_as_float((ef - 0x40000000u < 0x3F800000u) ? b2 : b);
}

__global__ void __launch_bounds__(THREADS) mute_kernel(
    const float4* __restrict__ x,
    const int* __restrict__ rows,
    const int* __restrict__ cols,
    float4* __restrict__ out)
{
    __shared__ unsigned char lut[HW4];

    int tid = threadIdx.x;
    if (tid < HW4) {
        int p = tid * 4;          // element offset within 28x28 image
        int h = p / 28;
        int w = p - h * 28;       // float4 never crosses a row (4 | 28)
        int r0 = rows[0], r1 = rows[1], r2 = rows[2], r3 = rows[3];
        int c0 = cols[0], c1 = cols[1], c2 = cols[2], c3 = cols[3];
        bool rm = (h == r0) | (h == r1) | (h == r2) | (h == r3);
        unsigned m = 0;
        #pragma unroll
        for (int k = 0; k < 4; k++) {
            bool cm = (w + k == c0) | (w + k == c1) | (w + k == c2) | (w + k == c3);
            if (rm | cm) m |= (1u << k);
        }
        lut[tid] = (unsigned char)m;
    }
    __syncthreads();

    int base = blockIdx.x * (THREADS * UNROLL) + tid;

    // Front-batch 4 LDG.128s (MLP=4), default caching
    float4 v[UNROLL];
    #pragma unroll
    for (int k = 0; k < UNROLL; k++) {
        v[k] = x[base + k * THREADS];
    }

    // Incremental phase: (base + k*THREADS) % 196
    int ph = base % HW4;

    #pragma unroll
    for (int k = 0; k < UNROLL; k++) {
        unsigned m = lut[ph];
        v[k].x = (m & 1u) ? mute1(v[k].x) : v[k].x;
        v[k].y = (m & 2u) ? mute1(v[k].y) : v[k].y;
        v[k].z = (m & 4u) ? mute1(v[k].z) : v[k].z;
        v[k].w = (m & 8u) ? mute1(v[k].w) : v[k].w;
        out[base + k * THREADS] = v[k];
        ph += STEP;
        if (ph >= HW4) ph -= HW4;
    }
}

extern "C" void kernel_launch(void* const* d_in, const int* in_sizes, int n_in,
                              void* d_out, int out_size) {
    const float4* x = (const float4*)d_in[0];
    const int* rows = (const int*)d_in[1];
    const int* cols = (const int*)d_in[2];
    float4* out     = (float4*)d_out;

    const int blocks = N4 / (THREADS * UNROLL);  // 12,544 exact
    mute_kernel<<<blocks, THREADS>>>(x, rows, cols, out);
}